// round 5
// baseline (speedup 1.0000x reference)
#include <cuda_runtime.h>

#define BB   4
#define NIN  128
#define NOUT 128
#define NN   256

// Scratch for the factorized projections Pi = Wi@node, Pj = Wj@node.
// (512 KB each — __device__ globals, allocation-free per harness rules.)
__device__ __align__(16) float g_pi[BB * NOUT * NN];
__device__ __align__(16) float g_pj[BB * NOUT * NN];

// Kernel 1: Pi[b,o,j] = sum_c Wi[o,c]*node[b,c,j]   (and same for Pj)
// grid = B*NOUT blocks, block = NN threads (one thread per j).
// node reads are coalesced across j; Wi/Wj reads are uniform per block (L1 hit).
__global__ void proj_kernel(const float* __restrict__ node,
                            const float* __restrict__ Wi,
                            const float* __restrict__ Wj) {
    const int j = threadIdx.x;            // 0..255
    const int o = blockIdx.x & (NOUT - 1);
    const int b = blockIdx.x >> 7;

    const float* np = node + b * NIN * NN + j;
    const float* wi = Wi + o * NIN;
    const float* wj = Wj + o * NIN;

    float ai = 0.0f, aj = 0.0f;
#pragma unroll 8
    for (int c = 0; c < NIN; ++c) {
        const float nv = __ldg(&np[c * NN]);
        ai = fmaf(__ldg(&wi[c]), nv, ai);
        aj = fmaf(__ldg(&wj[c]), nv, aj);
    }
    const int off = (b * NOUT + o) * NN + j;
    g_pi[off] = ai;
    g_pj[off] = aj;
}

// Kernel 2: out[b,o,i,j] = adj[b,i,j] * (i==j ? Pi[b,o,j] : Pj[b,o,j])
// One float4 (4 consecutive j) per thread -> pure STG.128 stream.
// adj and Pj are tiny and L2-resident; DRAM traffic ~= the 134 MB of stores.
__global__ void expand_kernel(const float4* __restrict__ adj,
                              float4* __restrict__ out) {
    const unsigned v  = blockIdx.x * blockDim.x + threadIdx.x; // float4 index
    const unsigned j4 = v & 63u;        // 256/4 float4 per row
    const unsigned r  = v >> 6;
    const unsigned i  = r & 255u;
    const unsigned r2 = r >> 8;
    const unsigned o  = r2 & 127u;
    const unsigned b  = r2 >> 7;

    const float4 a = __ldg(&adj[(b << 14) + (i << 6) + j4]);

    const float4* pj4 = reinterpret_cast<const float4*>(g_pj);
    const unsigned prow4 = ((b << 7) + o) << 6;   // row of 64 float4
    const float4 p = pj4[prow4 + j4];

    float4 res;
    res.x = a.x * p.x;
    res.y = a.y * p.y;
    res.z = a.z * p.z;
    res.w = a.w * p.w;

    // Diagonal element j==i lands in this float4 iff j4 == i>>2 (1/64 of threads).
    if (j4 == (i >> 2)) {
        const float piv = g_pi[(((b << 7) + o) << 8) + i];
        const unsigned lane = i & 3u;
        if      (lane == 0u) res.x = a.x * piv;
        else if (lane == 1u) res.y = a.y * piv;
        else if (lane == 2u) res.z = a.z * piv;
        else                 res.w = a.w * piv;
    }

    out[v] = res;
}

extern "C" void kernel_launch(void* const* d_in, const int* in_sizes, int n_in,
                              void* d_out, int out_size) {
    const float* adj  = (const float*)d_in[0];  // [B,1,N,N]
    const float* node = (const float*)d_in[1];  // [B,NIN,N]
    const float* Wi   = (const float*)d_in[2];  // [NOUT,NIN]
    const float* Wj   = (const float*)d_in[3];  // [NOUT,NIN]
    float* out = (float*)d_out;                 // [B,NOUT,N,N]

    (void)in_sizes; (void)n_in; (void)out_size;

    proj_kernel<<<BB * NOUT, NN>>>(node, Wi, Wj);

    const int total4 = BB * NOUT * NN * NN / 4;   // 8,388,608 float4
    expand_kernel<<<total4 / 256, 256>>>((const float4*)adj, (float4*)out);
}

// round 6
// speedup vs baseline: 1.5203x; 1.5203x over previous
#include <cuda_runtime.h>

#define BB   4
#define NIN  128
#define NOUT 128
#define NN   256

// Fused kernel: one block per (b, o).
//   Phase 1 (proj): thread j computes Pi[b,o,j], Pj[b,o,j] into smem.
//   Phase 2 (expand): thread (sub, j4) streams 64 rows i of the output tile:
//       out[b,o,i,j] = adj[b,i,j] * (i==j ? Pi[j] : Pj[j])
// Output stores use __stcs (evict-first) so the 134MB stream doesn't evict
// the hot adj/node/P data from L2.
__global__ void __launch_bounds__(256, 4)
fused_kernel(const float* __restrict__ node,
             const float* __restrict__ Wi,
             const float* __restrict__ Wj,
             const float4* __restrict__ adj,
             float4* __restrict__ out) {
    __shared__ float s_pi[NN];
    __shared__ __align__(16) float s_pj[NN];

    const int t = threadIdx.x;            // 0..255
    const int o = blockIdx.x & (NOUT - 1);
    const int b = blockIdx.x >> 7;

    // ---- Phase 1: Pi[j] = sum_c Wi[o,c]*node[b,c,j]  (j = t) ----
    {
        const float* np = node + b * NIN * NN + t;
        const float* wi = Wi + o * NIN;
        const float* wj = Wj + o * NIN;
        float ai = 0.0f, aj = 0.0f;
#pragma unroll 8
        for (int c = 0; c < NIN; ++c) {
            const float nv = __ldg(&np[c * NN]);
            ai = fmaf(__ldg(&wi[c]), nv, ai);
            aj = fmaf(__ldg(&wj[c]), nv, aj);
        }
        s_pi[t] = ai;
        s_pj[t] = aj;
    }
    __syncthreads();

    // ---- Phase 2: stream the 256x256 tile ----
    const int j4  = t & 63;               // float4 column index (4 j's)
    const int sub = t >> 6;               // 0..3, each owns 64 rows i

    const float4 p = reinterpret_cast<const float4*>(s_pj)[j4];

    const float4* adj_b  = adj + ((unsigned)b << 14);                 // [i][j4]
    float4*       out_bo = out + (((unsigned)(b << 7) + o) << 14);    // [i][j4]

    const int i_base = sub << 6;

#pragma unroll 4
    for (int g = 0; g < 16; ++g) {
        const int i0 = i_base + (g << 2);   // 4-aligned row group

        const float4 a0 = __ldg(&adj_b[((i0 + 0) << 6) + j4]);
        const float4 a1 = __ldg(&adj_b[((i0 + 1) << 6) + j4]);
        const float4 a2 = __ldg(&adj_b[((i0 + 2) << 6) + j4]);
        const float4 a3 = __ldg(&adj_b[((i0 + 3) << 6) + j4]);

        float4 r0, r1, r2, r3;
        r0.x = a0.x * p.x; r0.y = a0.y * p.y; r0.z = a0.z * p.z; r0.w = a0.w * p.w;
        r1.x = a1.x * p.x; r1.y = a1.y * p.y; r1.z = a1.z * p.z; r1.w = a1.w * p.w;
        r2.x = a2.x * p.x; r2.y = a2.y * p.y; r2.z = a2.z * p.z; r2.w = a2.w * p.w;
        r3.x = a3.x * p.x; r3.y = a3.y * p.y; r3.z = a3.z * p.z; r3.w = a3.w * p.w;

        // Diagonal: i>>2 == j4 for this 4-aligned group means rows i0..i0+3
        // carry diagonal elements at lanes 0..3 respectively.
        if ((i0 >> 2) == j4) {
            r0.x = a0.x * s_pi[i0 + 0];
            r1.y = a1.y * s_pi[i0 + 1];
            r2.z = a2.z * s_pi[i0 + 2];
            r3.w = a3.w * s_pi[i0 + 3];
        }

        __stcs(&out_bo[((i0 + 0) << 6) + j4], r0);
        __stcs(&out_bo[((i0 + 1) << 6) + j4], r1);
        __stcs(&out_bo[((i0 + 2) << 6) + j4], r2);
        __stcs(&out_bo[((i0 + 3) << 6) + j4], r3);
    }
}

extern "C" void kernel_launch(void* const* d_in, const int* in_sizes, int n_in,
                              void* d_out, int out_size) {
    const float* adj  = (const float*)d_in[0];  // [B,1,N,N]
    const float* node = (const float*)d_in[1];  // [B,NIN,N]
    const float* Wi   = (const float*)d_in[2];  // [NOUT,NIN]
    const float* Wj   = (const float*)d_in[3];  // [NOUT,NIN]
    float* out = (float*)d_out;                 // [B,NOUT,N,N]

    (void)in_sizes; (void)n_in; (void)out_size;

    fused_kernel<<<BB * NOUT, 256>>>(node, Wi, Wj, (const float4*)adj, (float4*)out);
}